// round 7
// baseline (speedup 1.0000x reference)
#include <cuda_runtime.h>
#include <cstddef>

// Problem constants
#define BB    128
#define DD    128
#define OUTSZ 100000
#define KP1   4097
#define NP    (BB * KP1)          // 524416 score elements per memory
#define INV_T (1.0f / 0.07f)
#define XBLK  9                   // ceil(KP1/512)
#define NPART (BB * XBLK)         // partial sums per memory (1152)
#define MEMN  ((size_t)OUTSZ * DD)

// Output layout (float32):
//   [0,            524416)   I_z12
//   [524416,      1048832)   I_z13
//   [1048832,    13848832)   new_mem2 (100000 x 128)
//   [13848832,   26648832)   new_mem3
#define OFF_I2   ((size_t)0)
#define OFF_I3   ((size_t)NP)
#define OFF_M2   ((size_t)2 * NP)
#define OFF_M3   ((size_t)2 * NP + MEMN)

// Z-reduction scratch lives at the START of the new_mem2 output region; it is
// consumed by reduce/norm and then OVERWRITTEN by copy_banks (same stream).
#define OFF_PART (OFF_M2)          // 2*NPART floats of partial sums
#define OFF_Z    (OFF_M2 + 4096)   // 2 floats (Z per memory)

// ---------------------------------------------------------------------------
// Score kernel: memory m = blockIdx.z, batch b = blockIdx.y, 512-wide k chunk
// = blockIdx.x. 4 lanes cooperate per (b,k). Row indices are CLAMPED to the
// valid range so a bad index can never fault (it would only perturb values).
// ---------------------------------------------------------------------------
__global__ void __launch_bounds__(256) score_kernel(
    const float* __restrict__ z1,
    const float* __restrict__ mem2,
    const float* __restrict__ mem3,
    const int*   __restrict__ y,
    const int*   __restrict__ idx,
    float*       __restrict__ out)
{
    const int m = blockIdx.z;
    const int b = blockIdx.y;
    const float* __restrict__ mem = m ? mem3 : mem2;
    float* __restrict__ o = out + (m ? OFF_I3 : OFF_I2) + (size_t)b * KP1;

    __shared__ float z1s[DD];
    __shared__ float sdot[256];
    __shared__ float red[256];

    const int tid = threadIdx.x;
    if (tid < DD) z1s[tid] = z1[b * DD + tid];
    __syncthreads();

    const int group = tid >> 2;   // 64 groups of 4 lanes
    const int lane  = tid & 3;

    float local = 0.0f;
    const int kbase = blockIdx.x * 512;

    #pragma unroll
    for (int it = 0; it < 8; ++it) {
        const int k = kbase + it * 64 + group;
        const bool valid = (k < KP1);
        int row;
        if (!valid)       row = 0;            // safe dummy load
        else if (k == 0)  row = y[b];
        else              row = idx[b * KP1 + k];
        // defensive clamp: faults become wrong values, not crashes
        row = row < 0 ? 0 : (row >= OUTSZ ? OUTSZ - 1 : row);

        const float* __restrict__ rf = mem + (size_t)row * DD;
        float acc = 0.0f;
        #pragma unroll
        for (int j = 0; j < 32; ++j) {
            const int e = j * 4 + lane;       // 4 lanes cover 16 contiguous B
            acc = fmaf(rf[e], z1s[e], acc);
        }

        sdot[tid] = acc;
        __syncthreads();
        if (lane == 0 && valid) {
            const float dot = sdot[tid] + sdot[tid + 1]
                            + sdot[tid + 2] + sdot[tid + 3];
            const float s = expf(dot * INV_T);
            o[k] = s;
            local += s;
        }
        __syncthreads();
    }

    red[tid] = local;
    __syncthreads();
    for (int off = 128; off > 0; off >>= 1) {
        if (tid < off) red[tid] += red[tid + off];
        __syncthreads();
    }
    if (tid == 0)
        out[OFF_PART + (size_t)(m * NPART + b * XBLK + blockIdx.x)] = red[0];
}

// Deterministic final reduction: one block per memory.
__global__ void __launch_bounds__(512) reduce_kernel(float* __restrict__ out)
{
    const int m = blockIdx.x;
    const int t = threadIdx.x;
    const float* __restrict__ part = out + OFF_PART + (size_t)m * NPART;

    float s = 0.0f;
    for (int i = t; i < NPART; i += 512)
        s += part[i];

    __shared__ float red[512];
    red[t] = s;
    __syncthreads();
    for (int off = 256; off > 0; off >>= 1) {
        if (t < off) red[t] += red[t + off];
        __syncthreads();
    }
    if (t == 0)
        out[OFF_Z + m] = red[0] / (float)NP * (float)OUTSZ;
}

// Normalize: out[i] = s / Z. Runs BEFORE copy_banks (Z lives in scratch).
__global__ void norm_kernel(float* __restrict__ out)
{
    const int i = blockIdx.x * blockDim.x + threadIdx.x;
    if (i < 2 * NP) {
        const float Z = out[OFF_Z + (i < NP ? 0 : 1)];
        out[i] = out[i] / Z;
    }
}

// Bank copy-out: pure 32-bit grid-stride copy.
__global__ void __launch_bounds__(256) copy_banks_kernel(
    const float* __restrict__ mem2,
    const float* __restrict__ mem3,
    float*       __restrict__ out)
{
    const size_t stride = (size_t)gridDim.x * blockDim.x;
    float* __restrict__ o2 = out + OFF_M2;
    float* __restrict__ o3 = out + OFF_M3;
    for (size_t i = (size_t)blockIdx.x * blockDim.x + threadIdx.x;
         i < MEMN; i += stride) {
        o2[i] = mem2[i];
        o3[i] = mem3[i];
    }
}

// Memory-row update: pos = 2*z - mem[y]; L2-normalize; scatter (last
// duplicate wins via predicated store).
__global__ void update_kernel(
    const float* __restrict__ z2,
    const float* __restrict__ z3,
    const float* __restrict__ mem2,
    const float* __restrict__ mem3,
    const int*   __restrict__ y,
    float*       __restrict__ out)
{
    const int i = blockIdx.x;   // batch row 0..127
    const int m = blockIdx.y;   // memory select
    const int d = threadIdx.x;  // 128 threads = D

    int yi = y[i];
    yi = yi < 0 ? 0 : (yi >= OUTSZ ? OUTSZ - 1 : yi);
    bool dead = false;
    for (int j = i + 1; j < BB; ++j)
        dead = dead || (y[j] == yi);

    const float* __restrict__ mem = m ? mem3 : mem2;
    const float* __restrict__ z   = m ? z3   : z2;

    const float v = 2.0f * z[i * DD + d] - mem[(size_t)yi * DD + d];

    __shared__ float ss[DD];
    ss[d] = v * v;
    __syncthreads();
    for (int off = 64; off > 0; off >>= 1) {
        if (d < off) ss[d] += ss[d + off];
        __syncthreads();
    }
    const float inv = 1.0f / sqrtf(ss[0]);

    if (!dead) {
        float* __restrict__ om = out + (m ? OFF_M3 : OFF_M2);
        om[(size_t)yi * DD + d] = v * inv;
    }
}

extern "C" void kernel_launch(void* const* d_in, const int* in_sizes, int n_in,
                              void* d_out, int out_size)
{
    // Identify inputs BY ELEMENT COUNT, not by position. Unique sizes:
    //   16384      -> z1, z2, z3      (relative order preserved)
    //   12800000   -> memory_z2, memory_z3 (relative order preserved)
    //   128        -> y
    //   524416     -> idx
    const float* zv[3]   = {0, 0, 0};
    const float* memv[2] = {0, 0};
    const int*   y   = 0;
    const int*   idx = 0;
    int nz = 0, nm = 0;
    for (int i = 0; i < n_in; ++i) {
        const int sz = in_sizes[i];
        if (sz == BB * DD) {
            if (nz < 3) zv[nz++] = (const float*)d_in[i];
        } else if (sz == (int)MEMN) {
            if (nm < 2) memv[nm++] = (const float*)d_in[i];
        } else if (sz == BB) {
            y = (const int*)d_in[i];
        } else if (sz == BB * KP1) {
            idx = (const int*)d_in[i];
        }
    }
    const float* z1   = zv[0];
    const float* z2   = zv[1];
    const float* z3   = zv[2];
    const float* mem2 = memv[0];
    const float* mem3 = memv[1];
    float* out = (float*)d_out;

    // 1) gathered score computation (raw exp values + per-block partials)
    dim3 sgrid(XBLK, BB, 2);
    score_kernel<<<sgrid, 256>>>(z1, mem2, mem3, y, idx, out);

    // 2) deterministic Z reduction
    reduce_kernel<<<2, 512>>>(out);

    // 3) normalize scores (consumes Z from scratch)
    const int n = 2 * NP;
    norm_kernel<<<(n + 255) / 256, 256>>>(out);

    // 4) bank copy-out (overwrites scratch with real data)
    copy_banks_kernel<<<2048, 256>>>(mem2, mem3, out);

    // 5) scatter the 128 updated rows into each copied memory
    dim3 ugrid(BB, 2);
    update_kernel<<<ugrid, DD>>>(z2, z3, mem2, mem3, y, out);
}

// round 8
// speedup vs baseline: 1.8771x; 1.8771x over previous
#include <cuda_runtime.h>
#include <cstddef>
#include <cstdint>

// Problem constants
#define BB    128
#define DD    128
#define OUTSZ 100000
#define KP1   4097
#define NP    (BB * KP1)          // 524416 score elements per memory
#define INV_T (1.0f / 0.07f)
#define XBLK  9                   // ceil(KP1/512)
#define NPART (BB * XBLK)         // partial sums per memory (1152)
#define MEMN  ((size_t)OUTSZ * DD)

// Output layout (float32):
//   [0,            524416)   I_z12
//   [524416,      1048832)   I_z13
//   [1048832,    13848832)   new_mem2 (100000 x 128)
//   [13848832,   26648832)   new_mem3
#define OFF_I2   ((size_t)0)
#define OFF_I3   ((size_t)NP)
#define OFF_M2   ((size_t)2 * NP)
#define OFF_M3   ((size_t)2 * NP + MEMN)

// Z-reduction scratch at the START of the new_mem2 output region; consumed by
// reduce/norm, then OVERWRITTEN by copy_banks (same stream => ordered).
#define OFF_PART (OFF_M2)          // 2*NPART floats of partial sums
#define OFF_Z    (OFF_M2 + 4096)   // 2 floats (Z per memory)

// ---------------------------------------------------------------------------
// Score kernel v2. Block = 256 threads = 8 warps; block handles (m =
// blockIdx.z, b = blockIdx.y, 512 k's at blockIdx.x*512). 8 lanes cooperate
// per k: lane gl of a group reads float4 #(j*8+gl) of the row (j=0..3), i.e.
// each group reads one full 128B line per warp load-slice. z1 lives in 4
// float4 registers per lane. Reduction = 3 converged shfl_xor. No barriers
// in the hot loop. VEC=false is the (verified-correct) scalar fallback.
// ---------------------------------------------------------------------------
template <bool VEC>
__global__ void __launch_bounds__(256) score_kernel(
    const float* __restrict__ z1,
    const float* __restrict__ mem2,
    const float* __restrict__ mem3,
    const int*   __restrict__ y,
    const int*   __restrict__ idx,
    float*       __restrict__ out)
{
    const int m = blockIdx.z;
    const int b = blockIdx.y;
    const float* __restrict__ mem = m ? mem3 : mem2;
    float* __restrict__ o = out + (m ? OFF_I3 : OFF_I2) + (size_t)b * KP1;

    const int tid  = threadIdx.x;
    const int warp = tid >> 5;
    const int lane = tid & 31;
    const int g    = lane >> 3;   // group 0..3 within warp
    const int gl   = lane & 7;    // lane within group

    // z1 -> registers: this lane's 16 fixed elements (j*32 + gl*16 bytes...)
    float4 zr[4];
    {
        const float* __restrict__ zb = z1 + b * DD;
        if (VEC) {
            const float4* __restrict__ z4 = (const float4*)zb;
            #pragma unroll
            for (int j = 0; j < 4; ++j) zr[j] = z4[j * 8 + gl];
        } else {
            #pragma unroll
            for (int j = 0; j < 4; ++j) {
                const int e = (j * 8 + gl) * 4;
                zr[j].x = zb[e + 0]; zr[j].y = zb[e + 1];
                zr[j].z = zb[e + 2]; zr[j].w = zb[e + 3];
            }
        }
    }

    const int yb = y[b];
    const int kbase = blockIdx.x * 512;
    float local = 0.0f;

    // 16 iterations; each warp covers 4 k's per iteration; no barriers.
    #pragma unroll 4
    for (int it = 0; it < 16; ++it) {
        const int k = kbase + it * 32 + warp * 4 + g;
        const bool valid = (k < KP1);
        int row;
        if (!valid)       row = 0;            // safe dummy load
        else if (k == 0)  row = yb;
        else              row = idx[b * KP1 + k];
        row = row < 0 ? 0 : (row >= OUTSZ ? OUTSZ - 1 : row);

        const float* __restrict__ rf = mem + (size_t)row * DD;
        float acc;
        if (VEC) {
            const float4* __restrict__ r4 = (const float4*)rf;
            float4 a0 = r4[0 * 8 + gl];
            float4 a1 = r4[1 * 8 + gl];
            float4 a2 = r4[2 * 8 + gl];
            float4 a3 = r4[3 * 8 + gl];
            acc  = a0.x * zr[0].x; acc = fmaf(a0.y, zr[0].y, acc);
            acc = fmaf(a0.z, zr[0].z, acc); acc = fmaf(a0.w, zr[0].w, acc);
            acc = fmaf(a1.x, zr[1].x, acc); acc = fmaf(a1.y, zr[1].y, acc);
            acc = fmaf(a1.z, zr[1].z, acc); acc = fmaf(a1.w, zr[1].w, acc);
            acc = fmaf(a2.x, zr[2].x, acc); acc = fmaf(a2.y, zr[2].y, acc);
            acc = fmaf(a2.z, zr[2].z, acc); acc = fmaf(a2.w, zr[2].w, acc);
            acc = fmaf(a3.x, zr[3].x, acc); acc = fmaf(a3.y, zr[3].y, acc);
            acc = fmaf(a3.z, zr[3].z, acc); acc = fmaf(a3.w, zr[3].w, acc);
        } else {
            acc = 0.0f;
            #pragma unroll
            for (int j = 0; j < 4; ++j) {
                const int e = (j * 8 + gl) * 4;
                acc = fmaf(rf[e + 0], zr[j].x, acc);
                acc = fmaf(rf[e + 1], zr[j].y, acc);
                acc = fmaf(rf[e + 2], zr[j].z, acc);
                acc = fmaf(rf[e + 3], zr[j].w, acc);
            }
        }
        // converged full-warp shuffles; xor 1,2,4 stays within the 8-lane group
        acc += __shfl_xor_sync(0xffffffffu, acc, 1);
        acc += __shfl_xor_sync(0xffffffffu, acc, 2);
        acc += __shfl_xor_sync(0xffffffffu, acc, 4);
        if (valid && gl == 0) {
            const float s = expf(acc * INV_T);
            o[k] = s;
            local += s;
        }
    }

    // Once-per-block deterministic reduction of partial sums.
    __shared__ float red[256];
    red[tid] = local;
    __syncthreads();
    for (int off = 128; off > 0; off >>= 1) {
        if (tid < off) red[tid] += red[tid + off];
        __syncthreads();
    }
    if (tid == 0)
        out[OFF_PART + (size_t)(m * NPART + b * XBLK + blockIdx.x)] = red[0];
}

// Deterministic final reduction: one block per memory.
__global__ void __launch_bounds__(512) reduce_kernel(float* __restrict__ out)
{
    const int m = blockIdx.x;
    const int t = threadIdx.x;
    const float* __restrict__ part = out + OFF_PART + (size_t)m * NPART;

    float s = 0.0f;
    for (int i = t; i < NPART; i += 512)
        s += part[i];

    __shared__ float red[512];
    red[t] = s;
    __syncthreads();
    for (int off = 256; off > 0; off >>= 1) {
        if (t < off) red[t] += red[t + off];
        __syncthreads();
    }
    if (t == 0)
        out[OFF_Z + m] = red[0] / (float)NP * (float)OUTSZ;
}

// Normalize: out[i] = s / Z. Runs BEFORE copy_banks (Z lives in scratch).
__global__ void norm_kernel(float* __restrict__ out)
{
    const int i = blockIdx.x * blockDim.x + threadIdx.x;
    if (i < 2 * NP) {
        const float Z = out[OFF_Z + (i < NP ? 0 : 1)];
        out[i] = out[i] / Z;
    }
}

// Bank copy-out, vectorized variant (MEMN % 4 == 0, offsets keep 16B align).
template <bool VEC>
__global__ void __launch_bounds__(256) copy_banks_kernel(
    const float* __restrict__ mem2,
    const float* __restrict__ mem3,
    float*       __restrict__ out)
{
    const size_t stride = (size_t)gridDim.x * blockDim.x;
    if (VEC) {
        const float4* __restrict__ s2 = (const float4*)mem2;
        const float4* __restrict__ s3 = (const float4*)mem3;
        float4* __restrict__ o2 = (float4*)(out + OFF_M2);
        float4* __restrict__ o3 = (float4*)(out + OFF_M3);
        const size_t n4 = MEMN / 4;
        for (size_t i = (size_t)blockIdx.x * blockDim.x + threadIdx.x;
             i < n4; i += stride) {
            o2[i] = s2[i];
            o3[i] = s3[i];
        }
    } else {
        float* __restrict__ o2 = out + OFF_M2;
        float* __restrict__ o3 = out + OFF_M3;
        for (size_t i = (size_t)blockIdx.x * blockDim.x + threadIdx.x;
             i < MEMN; i += stride) {
            o2[i] = mem2[i];
            o3[i] = mem3[i];
        }
    }
}

// Memory-row update: pos = 2*z - mem[y]; L2-normalize; scatter (last
// duplicate wins via predicated store).
__global__ void update_kernel(
    const float* __restrict__ z2,
    const float* __restrict__ z3,
    const float* __restrict__ mem2,
    const float* __restrict__ mem3,
    const int*   __restrict__ y,
    float*       __restrict__ out)
{
    const int i = blockIdx.x;   // batch row 0..127
    const int m = blockIdx.y;   // memory select
    const int d = threadIdx.x;  // 128 threads = D

    int yi = y[i];
    yi = yi < 0 ? 0 : (yi >= OUTSZ ? OUTSZ - 1 : yi);
    bool dead = false;
    for (int j = i + 1; j < BB; ++j)
        dead = dead || (y[j] == yi);

    const float* __restrict__ mem = m ? mem3 : mem2;
    const float* __restrict__ z   = m ? z3   : z2;

    const float v = 2.0f * z[i * DD + d] - mem[(size_t)yi * DD + d];

    __shared__ float ss[DD];
    ss[d] = v * v;
    __syncthreads();
    for (int off = 64; off > 0; off >>= 1) {
        if (d < off) ss[d] += ss[d + off];
        __syncthreads();
    }
    const float inv = 1.0f / sqrtf(ss[0]);

    if (!dead) {
        float* __restrict__ om = out + (m ? OFF_M3 : OFF_M2);
        om[(size_t)yi * DD + d] = v * inv;
    }
}

extern "C" void kernel_launch(void* const* d_in, const int* in_sizes, int n_in,
                              void* d_out, int out_size)
{
    // Identify inputs BY ELEMENT COUNT (order-robust). Unique sizes:
    //   16384    -> z1, z2, z3           (relative order preserved)
    //   12800000 -> memory_z2, memory_z3 (relative order preserved)
    //   128      -> y
    //   524416   -> idx
    const float* zv[3]   = {0, 0, 0};
    const float* memv[2] = {0, 0};
    const int*   y   = 0;
    const int*   idx = 0;
    int nz = 0, nm = 0;
    for (int i = 0; i < n_in; ++i) {
        const int sz = in_sizes[i];
        if (sz == BB * DD) {
            if (nz < 3) zv[nz++] = (const float*)d_in[i];
        } else if (sz == (int)MEMN) {
            if (nm < 2) memv[nm++] = (const float*)d_in[i];
        } else if (sz == BB) {
            y = (const int*)d_in[i];
        } else if (sz == BB * KP1) {
            idx = (const int*)d_in[i];
        }
    }
    const float* z1   = zv[0];
    const float* z2   = zv[1];
    const float* z3   = zv[2];
    const float* mem2 = memv[0];
    const float* mem3 = memv[1];
    float* out = (float*)d_out;

    const bool vec_in  = ((((uintptr_t)mem2) | ((uintptr_t)mem3)
                         | ((uintptr_t)z1)) & 0xF) == 0;
    const bool vec_out = vec_in && ((((uintptr_t)out)) & 0xF) == 0;

    // 1) gathered score computation (raw exp values + per-block partials)
    dim3 sgrid(XBLK, BB, 2);
    if (vec_in)
        score_kernel<true ><<<sgrid, 256>>>(z1, mem2, mem3, y, idx, out);
    else
        score_kernel<false><<<sgrid, 256>>>(z1, mem2, mem3, y, idx, out);

    // 2) deterministic Z reduction
    reduce_kernel<<<2, 512>>>(out);

    // 3) normalize scores (consumes Z from scratch)
    const int n = 2 * NP;
    norm_kernel<<<(n + 255) / 256, 256>>>(out);

    // 4) bank copy-out (overwrites scratch with real data)
    if (vec_out)
        copy_banks_kernel<true ><<<2048, 256>>>(mem2, mem3, out);
    else
        copy_banks_kernel<false><<<2048, 256>>>(mem2, mem3, out);

    // 5) scatter the 128 updated rows into each copied memory
    dim3 ugrid(BB, 2);
    update_kernel<<<ugrid, DD>>>(z2, z3, mem2, mem3, y, out);
}

// round 9
// speedup vs baseline: 2.1037x; 1.1207x over previous
#include <cuda_runtime.h>
#include <cstddef>
#include <cstdint>

// Problem constants
#define BB    128
#define DD    128
#define OUTSZ 100000
#define KP1   4097
#define NP    (BB * KP1)          // 524416 score elements per memory
#define INV_T (1.0f / 0.07f)
#define XBLK  9                   // ceil(KP1/512)
#define NPART (BB * XBLK)         // partial sums per memory (1152)
#define MEMN  ((size_t)OUTSZ * DD)

// Output layout (float32):
//   [0,            524416)   I_z12
//   [524416,      1048832)   I_z13
//   [1048832,    13848832)   new_mem2 (100000 x 128)
//   [13848832,   26648832)   new_mem3
#define OFF_I2   ((size_t)0)
#define OFF_I3   ((size_t)NP)
#define OFF_M2   ((size_t)2 * NP)
#define OFF_M3   ((size_t)2 * NP + MEMN)

// Z-reduction scratch in device globals (exonerated in Rounds 4-7: the old
// faults were mis-mapped input pointers). Every slot is fully rewritten
// every launch -> deterministic, no zeroing needed. This frees the output
// region so copy_banks can run CONCURRENTLY with score/reduce/norm.
__device__ float g_part[2 * NPART];
__device__ float g_Z[2];

// ---------------------------------------------------------------------------
// Score kernel. Block = 256 threads = 8 warps; handles (m = blockIdx.z,
// b = blockIdx.y, 512 k's at blockIdx.x*512). 8 lanes cooperate per k:
// each group reads one full 128B line per warp load-slice; z1 in registers;
// 3 converged shfl_xor; no barriers in the hot loop.
// ---------------------------------------------------------------------------
template <bool VEC>
__global__ void __launch_bounds__(256) score_kernel(
    const float* __restrict__ z1,
    const float* __restrict__ mem2,
    const float* __restrict__ mem3,
    const int*   __restrict__ y,
    const int*   __restrict__ idx,
    float*       __restrict__ out)
{
    const int m = blockIdx.z;
    const int b = blockIdx.y;
    const float* __restrict__ mem = m ? mem3 : mem2;
    float* __restrict__ o = out + (m ? OFF_I3 : OFF_I2) + (size_t)b * KP1;

    const int tid  = threadIdx.x;
    const int warp = tid >> 5;
    const int lane = tid & 31;
    const int g    = lane >> 3;   // group 0..3 within warp
    const int gl   = lane & 7;    // lane within group

    float4 zr[4];
    {
        const float* __restrict__ zb = z1 + b * DD;
        if (VEC) {
            const float4* __restrict__ z4 = (const float4*)zb;
            #pragma unroll
            for (int j = 0; j < 4; ++j) zr[j] = z4[j * 8 + gl];
        } else {
            #pragma unroll
            for (int j = 0; j < 4; ++j) {
                const int e = (j * 8 + gl) * 4;
                zr[j].x = zb[e + 0]; zr[j].y = zb[e + 1];
                zr[j].z = zb[e + 2]; zr[j].w = zb[e + 3];
            }
        }
    }

    const int yb = y[b];
    const int kbase = blockIdx.x * 512;
    float local = 0.0f;

    #pragma unroll 4
    for (int it = 0; it < 16; ++it) {
        const int k = kbase + it * 32 + warp * 4 + g;
        const bool valid = (k < KP1);
        int row;
        if (!valid)       row = 0;            // safe dummy load
        else if (k == 0)  row = yb;
        else              row = idx[b * KP1 + k];
        row = row < 0 ? 0 : (row >= OUTSZ ? OUTSZ - 1 : row);

        const float* __restrict__ rf = mem + (size_t)row * DD;
        float acc;
        if (VEC) {
            const float4* __restrict__ r4 = (const float4*)rf;
            float4 a0 = r4[0 * 8 + gl];
            float4 a1 = r4[1 * 8 + gl];
            float4 a2 = r4[2 * 8 + gl];
            float4 a3 = r4[3 * 8 + gl];
            acc  = a0.x * zr[0].x; acc = fmaf(a0.y, zr[0].y, acc);
            acc = fmaf(a0.z, zr[0].z, acc); acc = fmaf(a0.w, zr[0].w, acc);
            acc = fmaf(a1.x, zr[1].x, acc); acc = fmaf(a1.y, zr[1].y, acc);
            acc = fmaf(a1.z, zr[1].z, acc); acc = fmaf(a1.w, zr[1].w, acc);
            acc = fmaf(a2.x, zr[2].x, acc); acc = fmaf(a2.y, zr[2].y, acc);
            acc = fmaf(a2.z, zr[2].z, acc); acc = fmaf(a2.w, zr[2].w, acc);
            acc = fmaf(a3.x, zr[3].x, acc); acc = fmaf(a3.y, zr[3].y, acc);
            acc = fmaf(a3.z, zr[3].z, acc); acc = fmaf(a3.w, zr[3].w, acc);
        } else {
            acc = 0.0f;
            #pragma unroll
            for (int j = 0; j < 4; ++j) {
                const int e = (j * 8 + gl) * 4;
                acc = fmaf(rf[e + 0], zr[j].x, acc);
                acc = fmaf(rf[e + 1], zr[j].y, acc);
                acc = fmaf(rf[e + 2], zr[j].z, acc);
                acc = fmaf(rf[e + 3], zr[j].w, acc);
            }
        }
        acc += __shfl_xor_sync(0xffffffffu, acc, 1);
        acc += __shfl_xor_sync(0xffffffffu, acc, 2);
        acc += __shfl_xor_sync(0xffffffffu, acc, 4);
        if (valid && gl == 0) {
            const float s = expf(acc * INV_T);
            o[k] = s;
            local += s;
        }
    }

    __shared__ float red[256];
    red[tid] = local;
    __syncthreads();
    for (int off = 128; off > 0; off >>= 1) {
        if (tid < off) red[tid] += red[tid + off];
        __syncthreads();
    }
    if (tid == 0)
        g_part[m * NPART + b * XBLK + blockIdx.x] = red[0];
}

// Deterministic final reduction: one block per memory.
__global__ void __launch_bounds__(512) reduce_kernel()
{
    const int m = blockIdx.x;
    const int t = threadIdx.x;
    float s = 0.0f;
    for (int i = t; i < NPART; i += 512)
        s += g_part[m * NPART + i];

    __shared__ float red[512];
    red[t] = s;
    __syncthreads();
    for (int off = 256; off > 0; off >>= 1) {
        if (t < off) red[t] += red[t + off];
        __syncthreads();
    }
    if (t == 0)
        g_Z[m] = red[0] / (float)NP * (float)OUTSZ;
}

// Normalize: out[i] = s / Z.
__global__ void norm_kernel(float* __restrict__ out)
{
    const int i = blockIdx.x * blockDim.x + threadIdx.x;
    if (i < 2 * NP) {
        const float Z = g_Z[i < NP ? 0 : 1];
        out[i] = out[i] / Z;
    }
}

// Bank copy-out (independent branch; runs concurrently with score).
template <bool VEC>
__global__ void __launch_bounds__(256) copy_banks_kernel(
    const float* __restrict__ mem2,
    const float* __restrict__ mem3,
    float*       __restrict__ out)
{
    const size_t stride = (size_t)gridDim.x * blockDim.x;
    if (VEC) {
        const float4* __restrict__ s2 = (const float4*)mem2;
        const float4* __restrict__ s3 = (const float4*)mem3;
        float4* __restrict__ o2 = (float4*)(out + OFF_M2);
        float4* __restrict__ o3 = (float4*)(out + OFF_M3);
        const size_t n4 = MEMN / 4;
        for (size_t i = (size_t)blockIdx.x * blockDim.x + threadIdx.x;
             i < n4; i += stride) {
            o2[i] = s2[i];
            o3[i] = s3[i];
        }
    } else {
        float* __restrict__ o2 = out + OFF_M2;
        float* __restrict__ o3 = out + OFF_M3;
        for (size_t i = (size_t)blockIdx.x * blockDim.x + threadIdx.x;
             i < MEMN; i += stride) {
            o2[i] = mem2[i];
            o3[i] = mem3[i];
        }
    }
}

// Memory-row update: pos = 2*z - mem[y]; L2-normalize; scatter (last
// duplicate wins via predicated store).
__global__ void update_kernel(
    const float* __restrict__ z2,
    const float* __restrict__ z3,
    const float* __restrict__ mem2,
    const float* __restrict__ mem3,
    const int*   __restrict__ y,
    float*       __restrict__ out)
{
    const int i = blockIdx.x;   // batch row 0..127
    const int m = blockIdx.y;   // memory select
    const int d = threadIdx.x;  // 128 threads = D

    int yi = y[i];
    yi = yi < 0 ? 0 : (yi >= OUTSZ ? OUTSZ - 1 : yi);
    bool dead = false;
    for (int j = i + 1; j < BB; ++j)
        dead = dead || (y[j] == yi);

    const float* __restrict__ mem = m ? mem3 : mem2;
    const float* __restrict__ z   = m ? z3   : z2;

    const float v = 2.0f * z[i * DD + d] - mem[(size_t)yi * DD + d];

    __shared__ float ss[DD];
    ss[d] = v * v;
    __syncthreads();
    for (int off = 64; off > 0; off >>= 1) {
        if (d < off) ss[d] += ss[d + off];
        __syncthreads();
    }
    const float inv = 1.0f / sqrtf(ss[0]);

    if (!dead) {
        float* __restrict__ om = out + (m ? OFF_M3 : OFF_M2);
        om[(size_t)yi * DD + d] = v * inv;
    }
}

extern "C" void kernel_launch(void* const* d_in, const int* in_sizes, int n_in,
                              void* d_out, int out_size)
{
    // Identify inputs BY ELEMENT COUNT (order-robust):
    //   16384    -> z1, z2, z3           (relative order preserved)
    //   12800000 -> memory_z2, memory_z3 (relative order preserved)
    //   128      -> y
    //   524416   -> idx
    const float* zv[3]   = {0, 0, 0};
    const float* memv[2] = {0, 0};
    const int*   y   = 0;
    const int*   idx = 0;
    int nz = 0, nm = 0;
    for (int i = 0; i < n_in; ++i) {
        const int sz = in_sizes[i];
        if (sz == BB * DD) {
            if (nz < 3) zv[nz++] = (const float*)d_in[i];
        } else if (sz == (int)MEMN) {
            if (nm < 2) memv[nm++] = (const float*)d_in[i];
        } else if (sz == BB) {
            y = (const int*)d_in[i];
        } else if (sz == BB * KP1) {
            idx = (const int*)d_in[i];
        }
    }
    const float* z1   = zv[0];
    const float* z2   = zv[1];
    const float* z3   = zv[2];
    const float* mem2 = memv[0];
    const float* mem3 = memv[1];
    float* out = (float*)d_out;

    const bool vec_in  = ((((uintptr_t)mem2) | ((uintptr_t)mem3)
                         | ((uintptr_t)z1)) & 0xF) == 0;
    const bool vec_out = vec_in && ((((uintptr_t)out)) & 0xF) == 0;

    // One side stream + fork/join events (created once; capture-compatible).
    static cudaStream_t sB = 0;
    static cudaEvent_t evFork = 0, evJoin = 0;
    if (sB == 0) {
        cudaStreamCreateWithFlags(&sB, cudaStreamNonBlocking);
        cudaEventCreateWithFlags(&evFork, cudaEventDisableTiming);
        cudaEventCreateWithFlags(&evJoin, cudaEventDisableTiming);
    }

    // Fork: branch B (DRAM-heavy copy + row update) runs concurrently with
    // branch A (L2-heavy score -> reduce -> norm). The two branches touch
    // disjoint output regions; Z scratch is in device globals.
    cudaEventRecord(evFork, 0);
    cudaStreamWaitEvent(sB, evFork, 0);

    // Branch B on sB
    if (vec_out)
        copy_banks_kernel<true ><<<2048, 256, 0, sB>>>(mem2, mem3, out);
    else
        copy_banks_kernel<false><<<2048, 256, 0, sB>>>(mem2, mem3, out);
    dim3 ugrid(BB, 2);
    update_kernel<<<ugrid, DD, 0, sB>>>(z2, z3, mem2, mem3, y, out);
    cudaEventRecord(evJoin, sB);

    // Branch A on the default (capture) stream
    dim3 sgrid(XBLK, BB, 2);
    if (vec_in)
        score_kernel<true ><<<sgrid, 256>>>(z1, mem2, mem3, y, idx, out);
    else
        score_kernel<false><<<sgrid, 256>>>(z1, mem2, mem3, y, idx, out);
    reduce_kernel<<<2, 512>>>();
    const int n = 2 * NP;
    norm_kernel<<<(n + 255) / 256, 256>>>(out);

    // Join
    cudaStreamWaitEvent(0, evJoin, 0);
}